// round 5
// baseline (speedup 1.0000x reference)
#include <cuda_runtime.h>
#include <cuda_bf16.h>

#define EPS 1e-6f

__global__ __launch_bounds__(256) void HardPhongShader_kernel(
    const int*   __restrict__ p2f,      // (N,H,W,1)
    const float* __restrict__ bary,     // (N,H,W,1,3)
    const float* __restrict__ verts,    // (V,3)
    const float* __restrict__ vnorm,    // (V,3)
    const float* __restrict__ vcol,     // (V,3)
    const int*   __restrict__ faces,    // (F,3)
    const float* __restrict__ lloc,     // (N,3)
    const float* __restrict__ l_amb,    // (1,3)
    const float* __restrict__ l_dif,    // (1,3)
    const float* __restrict__ l_spec,   // (1,3)
    const float* __restrict__ m_amb,    // (1,3)
    const float* __restrict__ m_dif,    // (1,3)
    const float* __restrict__ m_spec,   // (1,3)
    const float* __restrict__ shin,     // (1,)
    const float* __restrict__ cam,      // (N,3)
    const float* __restrict__ bg,       // (3,)
    float4*      __restrict__ out,      // (N,H,W,4)
    int total, int HW)
{
    int i = blockIdx.x * blockDim.x + threadIdx.x;
    if (i >= total) return;

    int f = p2f[i];
    if (f < 0) {
        out[i] = make_float4(bg[0], bg[1], bg[2], 0.0f);
        return;
    }

    // barycentric weights
    float b0 = bary[3*i + 0];
    float b1 = bary[3*i + 1];
    float b2 = bary[3*i + 2];

    // face -> vertex indices
    int v0 = faces[3*f + 0];
    int v1 = faces[3*f + 1];
    int v2 = faces[3*f + 2];

    // interpolated position
    float px = b0*verts[3*v0+0] + b1*verts[3*v1+0] + b2*verts[3*v2+0];
    float py = b0*verts[3*v0+1] + b1*verts[3*v1+1] + b2*verts[3*v2+1];
    float pz = b0*verts[3*v0+2] + b1*verts[3*v1+2] + b2*verts[3*v2+2];

    // interpolated normal (verts_normals are unit, interp is not)
    float nx = b0*vnorm[3*v0+0] + b1*vnorm[3*v1+0] + b2*vnorm[3*v2+0];
    float ny = b0*vnorm[3*v0+1] + b1*vnorm[3*v1+1] + b2*vnorm[3*v2+1];
    float nz = b0*vnorm[3*v0+2] + b1*vnorm[3*v1+2] + b2*vnorm[3*v2+2];

    // interpolated texel color
    float tr = b0*vcol[3*v0+0] + b1*vcol[3*v1+0] + b2*vcol[3*v2+0];
    float tg = b0*vcol[3*v0+1] + b1*vcol[3*v1+1] + b2*vcol[3*v2+1];
    float tb = b0*vcol[3*v0+2] + b1*vcol[3*v1+2] + b2*vcol[3*v2+2];

    int nb = i / HW;   // batch index

    // normalize normal:  x / max(||x||, EPS)
    {
        float nn  = sqrtf(nx*nx + ny*ny + nz*nz);
        float inv = 1.0f / fmaxf(nn, EPS);
        nx *= inv; ny *= inv; nz *= inv;
    }

    // to_light = normalize(light_loc - point)
    float tlx = lloc[3*nb+0] - px;
    float tly = lloc[3*nb+1] - py;
    float tlz = lloc[3*nb+2] - pz;
    {
        float nn  = sqrtf(tlx*tlx + tly*tly + tlz*tlz);
        float inv = 1.0f / fmaxf(nn, EPS);
        tlx *= inv; tly *= inv; tlz *= inv;
    }

    float cosang = nx*tlx + ny*tly + nz*tlz;
    float dmax   = fmaxf(cosang, 0.0f);

    // specular (smask = cosang > 0 collapsed into branch)
    float spec = 0.0f;
    if (cosang > 0.0f) {
        // view_dir = normalize(cam - point)
        float vx = cam[3*nb+0] - px;
        float vy = cam[3*nb+1] - py;
        float vz = cam[3*nb+2] - pz;
        float nn  = sqrtf(vx*vx + vy*vy + vz*vz);
        float inv = 1.0f / fmaxf(nn, EPS);
        vx *= inv; vy *= inv; vz *= inv;

        // reflect = -to_light + 2*cos*n
        float c2 = 2.0f * cosang;
        float rx = c2*nx - tlx;
        float ry = c2*ny - tly;
        float rz = c2*nz - tlz;

        float alpha = fmaxf(vx*rx + vy*ry + vz*rz, 0.0f);
        if (alpha > 0.0f)
            spec = __powf(alpha, shin[0]);
    }

    // colors = (mat_amb*light_amb + mat_dif*light_dif*dmax) * texel + mat_spec*light_spec*spec
    float cr = (m_amb[0]*l_amb[0] + m_dif[0]*l_dif[0]*dmax) * tr + m_spec[0]*l_spec[0]*spec;
    float cg = (m_amb[1]*l_amb[1] + m_dif[1]*l_dif[1]*dmax) * tg + m_spec[1]*l_spec[1]*spec;
    float cb = (m_amb[2]*l_amb[2] + m_dif[2]*l_dif[2]*dmax) * tb + m_spec[2]*l_spec[2]*spec;

    out[i] = make_float4(cr, cg, cb, 1.0f);
}

extern "C" void kernel_launch(void* const* d_in, const int* in_sizes, int n_in,
                              void* d_out, int out_size) {
    const int*   p2f    = (const int*)  d_in[0];
    const float* bary   = (const float*)d_in[1];
    const float* verts  = (const float*)d_in[2];
    const float* vnorm  = (const float*)d_in[3];
    const float* vcol   = (const float*)d_in[4];
    const int*   faces  = (const int*)  d_in[5];
    const float* lloc   = (const float*)d_in[6];
    const float* l_amb  = (const float*)d_in[7];
    const float* l_dif  = (const float*)d_in[8];
    const float* l_spec = (const float*)d_in[9];
    const float* m_amb  = (const float*)d_in[10];
    const float* m_dif  = (const float*)d_in[11];
    const float* m_spec = (const float*)d_in[12];
    const float* shin   = (const float*)d_in[13];
    const float* cam    = (const float*)d_in[14];
    const float* bg     = (const float*)d_in[15];

    int total = in_sizes[0];          // N*H*W*K, K=1
    int N     = in_sizes[6] / 3;      // light_location is (N,3)
    int HW    = total / N;

    int threads = 256;
    int blocks  = (total + threads - 1) / threads;
    HardPhongShader_kernel<<<blocks, threads>>>(
        p2f, bary, verts, vnorm, vcol, faces, lloc,
        l_amb, l_dif, l_spec, m_amb, m_dif, m_spec, shin, cam, bg,
        (float4*)d_out, total, HW);
}

// round 6
// speedup vs baseline: 1.4966x; 1.4966x over previous
#include <cuda_runtime.h>
#include <cuda_bf16.h>

#define EPS 1e-6f

// Packed per-face attribute records: 36 floats used, padded to 40 floats
// (160 B = exactly 5 L2 sectors, 32B-aligned) per face.
// Layout: p0(3) p1(3) p2(3) n0(3) n1(3) n2(3) c0(3) c1(3) c2(3) pad(4)
#define MAX_FACES 204800
__device__ float g_packed[(size_t)MAX_FACES * 40];

__global__ __launch_bounds__(256) void prepack_kernel(
    const int*   __restrict__ faces,
    const float* __restrict__ verts,
    const float* __restrict__ vnorm,
    const float* __restrict__ vcol,
    int F)
{
    int f = blockIdx.x * blockDim.x + threadIdx.x;
    if (f >= F) return;

    int v0 = faces[3*f + 0];
    int v1 = faces[3*f + 1];
    int v2 = faces[3*f + 2];

    float a[36];
    #pragma unroll
    for (int k = 0; k < 3; k++) {
        int v = (k == 0) ? v0 : (k == 1) ? v1 : v2;
        a[ 0 + 3*k + 0] = verts[3*v + 0];
        a[ 0 + 3*k + 1] = verts[3*v + 1];
        a[ 0 + 3*k + 2] = verts[3*v + 2];
        a[ 9 + 3*k + 0] = vnorm[3*v + 0];
        a[ 9 + 3*k + 1] = vnorm[3*v + 1];
        a[ 9 + 3*k + 2] = vnorm[3*v + 2];
        a[18 + 3*k + 0] = vcol[3*v + 0];
        a[18 + 3*k + 1] = vcol[3*v + 1];
        a[18 + 3*k + 2] = vcol[3*v + 2];
    }

    float4* o = (float4*)(g_packed + (size_t)f * 40);
    #pragma unroll
    for (int j = 0; j < 9; j++)
        o[j] = make_float4(a[4*j+0], a[4*j+1], a[4*j+2], a[4*j+3]);
}

__device__ __forceinline__ void shade_and_store(
    float px, float py, float pz,
    float nx, float ny, float nz,
    float tr, float tg, float tb,
    float lx, float ly, float lz,
    float cx, float cy, float cz,
    const float* l_amb, const float* l_dif, const float* l_spec,
    const float* m_amb, const float* m_dif, const float* m_spec,
    float sh, float4* outp)
{
    // normalize normal
    {
        float nn  = sqrtf(nx*nx + ny*ny + nz*nz);
        float inv = 1.0f / fmaxf(nn, EPS);
        nx *= inv; ny *= inv; nz *= inv;
    }
    // to_light
    float tlx = lx - px, tly = ly - py, tlz = lz - pz;
    {
        float nn  = sqrtf(tlx*tlx + tly*tly + tlz*tlz);
        float inv = 1.0f / fmaxf(nn, EPS);
        tlx *= inv; tly *= inv; tlz *= inv;
    }
    float cosang = nx*tlx + ny*tly + nz*tlz;
    float dmax   = fmaxf(cosang, 0.0f);

    float spec = 0.0f;
    if (cosang > 0.0f) {
        float vx = cx - px, vy = cy - py, vz = cz - pz;
        float nn  = sqrtf(vx*vx + vy*vy + vz*vz);
        float inv = 1.0f / fmaxf(nn, EPS);
        vx *= inv; vy *= inv; vz *= inv;

        float c2 = 2.0f * cosang;
        float rx = c2*nx - tlx;
        float ry = c2*ny - tly;
        float rz = c2*nz - tlz;

        float alpha = fmaxf(vx*rx + vy*ry + vz*rz, 0.0f);
        if (alpha > 0.0f)
            spec = __powf(alpha, sh);
    }

    float cr = (m_amb[0]*l_amb[0] + m_dif[0]*l_dif[0]*dmax) * tr + m_spec[0]*l_spec[0]*spec;
    float cg = (m_amb[1]*l_amb[1] + m_dif[1]*l_dif[1]*dmax) * tg + m_spec[1]*l_spec[1]*spec;
    float cb = (m_amb[2]*l_amb[2] + m_dif[2]*l_dif[2]*dmax) * tb + m_spec[2]*l_spec[2]*spec;

    *outp = make_float4(cr, cg, cb, 1.0f);
}

// Fast path: reads packed face records (9x LDG.128 from one 160B span).
__global__ __launch_bounds__(256) void shade_packed_kernel(
    const int*   __restrict__ p2f,
    const float* __restrict__ bary,
    const float* __restrict__ lloc,
    const float* __restrict__ l_amb,
    const float* __restrict__ l_dif,
    const float* __restrict__ l_spec,
    const float* __restrict__ m_amb,
    const float* __restrict__ m_dif,
    const float* __restrict__ m_spec,
    const float* __restrict__ shin,
    const float* __restrict__ cam,
    const float* __restrict__ bg,
    float4*      __restrict__ out,
    int HW)
{
    int pix = blockIdx.x * blockDim.x + threadIdx.x;
    if (pix >= HW) return;
    int nb = blockIdx.y;
    int i  = nb * HW + pix;

    int f = p2f[i];
    if (f < 0) {
        out[i] = make_float4(bg[0], bg[1], bg[2], 0.0f);
        return;
    }

    float b0 = bary[3*i + 0];
    float b1 = bary[3*i + 1];
    float b2 = bary[3*i + 2];

    const float4* q = (const float4*)(g_packed + (size_t)f * 40);
    float a[36];
    #pragma unroll
    for (int j = 0; j < 9; j++) {
        float4 t = q[j];
        a[4*j+0] = t.x; a[4*j+1] = t.y; a[4*j+2] = t.z; a[4*j+3] = t.w;
    }

    float px = b0*a[0] + b1*a[3] + b2*a[6];
    float py = b0*a[1] + b1*a[4] + b2*a[7];
    float pz = b0*a[2] + b1*a[5] + b2*a[8];

    float nx = b0*a[ 9] + b1*a[12] + b2*a[15];
    float ny = b0*a[10] + b1*a[13] + b2*a[16];
    float nz = b0*a[11] + b1*a[14] + b2*a[17];

    float tr = b0*a[18] + b1*a[21] + b2*a[24];
    float tg = b0*a[19] + b1*a[22] + b2*a[25];
    float tb = b0*a[20] + b1*a[23] + b2*a[26];

    shade_and_store(px, py, pz, nx, ny, nz, tr, tg, tb,
                    lloc[3*nb+0], lloc[3*nb+1], lloc[3*nb+2],
                    cam[3*nb+0],  cam[3*nb+1],  cam[3*nb+2],
                    l_amb, l_dif, l_spec, m_amb, m_dif, m_spec,
                    shin[0], &out[i]);
}

// Fallback path (F > MAX_FACES): direct gathers, same as round-4 kernel.
__global__ __launch_bounds__(256) void shade_direct_kernel(
    const int*   __restrict__ p2f,
    const float* __restrict__ bary,
    const float* __restrict__ verts,
    const float* __restrict__ vnorm,
    const float* __restrict__ vcol,
    const int*   __restrict__ faces,
    const float* __restrict__ lloc,
    const float* __restrict__ l_amb,
    const float* __restrict__ l_dif,
    const float* __restrict__ l_spec,
    const float* __restrict__ m_amb,
    const float* __restrict__ m_dif,
    const float* __restrict__ m_spec,
    const float* __restrict__ shin,
    const float* __restrict__ cam,
    const float* __restrict__ bg,
    float4*      __restrict__ out,
    int HW)
{
    int pix = blockIdx.x * blockDim.x + threadIdx.x;
    if (pix >= HW) return;
    int nb = blockIdx.y;
    int i  = nb * HW + pix;

    int f = p2f[i];
    if (f < 0) {
        out[i] = make_float4(bg[0], bg[1], bg[2], 0.0f);
        return;
    }

    float b0 = bary[3*i + 0];
    float b1 = bary[3*i + 1];
    float b2 = bary[3*i + 2];

    int v0 = faces[3*f + 0];
    int v1 = faces[3*f + 1];
    int v2 = faces[3*f + 2];

    float px = b0*verts[3*v0+0] + b1*verts[3*v1+0] + b2*verts[3*v2+0];
    float py = b0*verts[3*v0+1] + b1*verts[3*v1+1] + b2*verts[3*v2+1];
    float pz = b0*verts[3*v0+2] + b1*verts[3*v1+2] + b2*verts[3*v2+2];

    float nx = b0*vnorm[3*v0+0] + b1*vnorm[3*v1+0] + b2*vnorm[3*v2+0];
    float ny = b0*vnorm[3*v0+1] + b1*vnorm[3*v1+1] + b2*vnorm[3*v2+1];
    float nz = b0*vnorm[3*v0+2] + b1*vnorm[3*v1+2] + b2*vnorm[3*v2+2];

    float tr = b0*vcol[3*v0+0] + b1*vcol[3*v1+0] + b2*vcol[3*v2+0];
    float tg = b0*vcol[3*v0+1] + b1*vcol[3*v1+1] + b2*vcol[3*v2+1];
    float tb = b0*vcol[3*v0+2] + b1*vcol[3*v1+2] + b2*vcol[3*v2+2];

    shade_and_store(px, py, pz, nx, ny, nz, tr, tg, tb,
                    lloc[3*nb+0], lloc[3*nb+1], lloc[3*nb+2],
                    cam[3*nb+0],  cam[3*nb+1],  cam[3*nb+2],
                    l_amb, l_dif, l_spec, m_amb, m_dif, m_spec,
                    shin[0], &out[i]);
}

extern "C" void kernel_launch(void* const* d_in, const int* in_sizes, int n_in,
                              void* d_out, int out_size) {
    const int*   p2f    = (const int*)  d_in[0];
    const float* bary   = (const float*)d_in[1];
    const float* verts  = (const float*)d_in[2];
    const float* vnorm  = (const float*)d_in[3];
    const float* vcol   = (const float*)d_in[4];
    const int*   faces  = (const int*)  d_in[5];
    const float* lloc   = (const float*)d_in[6];
    const float* l_amb  = (const float*)d_in[7];
    const float* l_dif  = (const float*)d_in[8];
    const float* l_spec = (const float*)d_in[9];
    const float* m_amb  = (const float*)d_in[10];
    const float* m_dif  = (const float*)d_in[11];
    const float* m_spec = (const float*)d_in[12];
    const float* shin   = (const float*)d_in[13];
    const float* cam    = (const float*)d_in[14];
    const float* bg     = (const float*)d_in[15];

    int total = in_sizes[0];          // N*H*W*K, K=1
    int N     = in_sizes[6] / 3;      // light_location is (N,3)
    int HW    = total / N;
    int F     = in_sizes[5] / 3;      // faces is (F,3)

    int threads = 256;
    dim3 grid((HW + threads - 1) / threads, N);

    if (F <= MAX_FACES) {
        prepack_kernel<<<(F + threads - 1) / threads, threads>>>(
            faces, verts, vnorm, vcol, F);
        shade_packed_kernel<<<grid, threads>>>(
            p2f, bary, lloc,
            l_amb, l_dif, l_spec, m_amb, m_dif, m_spec, shin, cam, bg,
            (float4*)d_out, HW);
    } else {
        shade_direct_kernel<<<grid, threads>>>(
            p2f, bary, verts, vnorm, vcol, faces, lloc,
            l_amb, l_dif, l_spec, m_amb, m_dif, m_spec, shin, cam, bg,
            (float4*)d_out, HW);
    }
}